// round 10
// baseline (speedup 1.0000x reference)
#include <cuda_runtime.h>
#include <cstdint>

// FeaturesLoss via mma.sync e4m3 m16n8k32 (compute_103-safe), persistent CTAs.
// R10: remove the 2-blocks register cap (was forcing spills: issue 48.6% vs
// ~11% architectural), 4-stage ring with 3 chunks in flight, inline-B MMAs.

#define BM 128
#define BN 128
#define BK 64            // fp8 bytes per K-chunk
#define NTHREADS 256
#define MAXN 4096
#define MAXD 512
#define SSTRB 80         // smem row stride bytes: conflict-free 16B granules
#define NSTG 4

#define STAGE_OP_BYTES (BM * SSTRB)          // 10240 per operand per stage
#define SM_A 0
#define SM_B (NSTG * STAGE_OP_BYTES)          // 40960
#define SM_SQA (2 * NSTG * STAGE_OP_BYTES)    // 81920
#define SM_SQB (SM_SQA + 512)
#define SM_LABA (SM_SQB + 512)
#define SM_LABB (SM_LABA + 512)
#define SM_RED (SM_LABB + 512)
#define SMEM_TOTAL (SM_RED + 128)             // 84096

__device__ float g_sq[MAXN];
__device__ __align__(16) uint8_t g_Xf8[MAXN * MAXD];
__device__ double g_sum1;
__device__ double g_sum2;
__device__ unsigned long long g_cnt;
__device__ unsigned int g_done;

__device__ __forceinline__ uint32_t smem_u32(const void* p) {
    uint32_t a;
    asm("{ .reg .u64 t; cvta.to.shared.u64 t, %1; cvt.u32.u64 %0, t; }"
        : "=r"(a) : "l"(p));
    return a;
}

#define CP_ASYNC16(dst_u32, src) \
    asm volatile("cp.async.cg.shared.global [%0], [%1], 16;" :: "r"(dst_u32), "l"(src))
#define CP_COMMIT() asm volatile("cp.async.commit_group;" ::: "memory")
#define CP_WAIT2()  asm volatile("cp.async.wait_group 2;" ::: "memory")

#define LDSM_X4(r0, r1, r2, r3, a)                                        \
    asm volatile("ldmatrix.sync.aligned.m8n8.x4.shared.b16 "              \
                 "{%0,%1,%2,%3}, [%4];"                                   \
                 : "=r"(r0), "=r"(r1), "=r"(r2), "=r"(r3) : "r"(a))

#define MMA16832(c, a0, a1, a2, a3, b0, b1)                               \
    asm volatile("mma.sync.aligned.m16n8k32.row.col.f32.e4m3.e4m3.f32 "   \
                 "{%0,%1,%2,%3}, {%4,%5,%6,%7}, {%8,%9}, {%0,%1,%2,%3};"  \
                 : "+f"((c)[0]), "+f"((c)[1]), "+f"((c)[2]), "+f"((c)[3]) \
                 : "r"(a0), "r"(a1), "r"(a2), "r"(a3), "r"(b0), "r"(b1))

__device__ __forceinline__ uint32_t pack_e4m3x4(float4 v) {
    uint16_t lo, hi;
    asm("cvt.rn.satfinite.e4m3x2.f32 %0, %1, %2;" : "=h"(lo) : "f"(v.y), "f"(v.x));
    asm("cvt.rn.satfinite.e4m3x2.f32 %0, %1, %2;" : "=h"(hi) : "f"(v.w), "f"(v.z));
    return (uint32_t)lo | ((uint32_t)hi << 16);
}

__device__ __forceinline__ void decode_tile(int t, int nt, int& br, int& bc) {
    int b = t, r = 0, rl = nt;
    while (b >= rl) {
        b -= rl;
        rl--;
        r++;
    }
    br = r;
    bc = r + b;
}

// ---------------------------------------------------------------------------
// Kernel A: X -> e4m3 + exact fp32 row norms. One warp per row.
// ---------------------------------------------------------------------------
__global__ void __launch_bounds__(128) convert_kernel(const float* __restrict__ X,
                                                      int n, int d) {
    if (blockIdx.x == 0 && threadIdx.x == 0) {
        g_sum1 = 0.0;
        g_sum2 = 0.0;
        g_cnt = 0ull;
        g_done = 0u;
    }
    const int w = threadIdx.x >> 5, l = threadIdx.x & 31;
    const int row = blockIdx.x * 4 + w;
    if (row >= n) return;
    const float4* src = reinterpret_cast<const float4*>(X + (size_t)row * d);
    uint32_t* dst = reinterpret_cast<uint32_t*>(g_Xf8 + (size_t)row * d);
    float s = 0.0f;
    if (d == 512) {
        float4 v[4];
#pragma unroll
        for (int i = 0; i < 4; i++) v[i] = src[l + 32 * i];
#pragma unroll
        for (int i = 0; i < 4; i++) {
            s = fmaf(v[i].x, v[i].x,
                     fmaf(v[i].y, v[i].y,
                          fmaf(v[i].z, v[i].z, fmaf(v[i].w, v[i].w, s))));
            dst[l + 32 * i] = pack_e4m3x4(v[i]);
        }
    } else {
        for (int c4 = l; c4 * 4 < d; c4 += 32) {
            float4 v = src[c4];
            s = fmaf(v.x, v.x, fmaf(v.y, v.y, fmaf(v.z, v.z, fmaf(v.w, v.w, s))));
            dst[c4] = pack_e4m3x4(v);
        }
    }
#pragma unroll
    for (int o = 16; o > 0; o >>= 1) s += __shfl_down_sync(0xffffffffu, s, o);
    if (l == 0) g_sq[row] = s;
}

// ---------------------------------------------------------------------------
// Kernel B: persistent fp8 Gram over tile stream + fused epilogue + finalize.
// NOTE: no min-blocks clause — let ptxas allocate true register demand.
// ---------------------------------------------------------------------------
__global__ void __launch_bounds__(NTHREADS) pair_kernel(
    const int* __restrict__ lab, const float* __restrict__ marginp,
    float* __restrict__ out, int n, int d, int nt, int nb) {
    extern __shared__ __align__(1024) uint8_t smem[];
    const uint32_t sbase = smem_u32(smem);
    float* sqA = reinterpret_cast<float*>(smem + SM_SQA);
    float* sqB = reinterpret_cast<float*>(smem + SM_SQB);
    int* labA = reinterpret_cast<int*>(smem + SM_LABA);
    int* labB = reinterpret_cast<int*>(smem + SM_LABB);

    const int tid = threadIdx.x;
    const int wid = tid >> 5, lane = tid & 31;
    const int warpM = wid & 3;   // 4 warps over M: 32 rows each
    const int warpN = wid >> 2;  // 2 warps over N: 64 cols each

    const int nChunks = d / BK;  // 8 for d=512
    const int stride = gridDim.x;
    int myTiles = 0;
    for (int t = blockIdx.x; t < nb; t += stride) myTiles++;
    const int total = myTiles * nChunks;

    const uint8_t* __restrict__ Xb = g_Xf8;
    const float margin = *marginp;

    // Per-thread load-slot geometry (constant across chunks/tiles).
    const int ldR0 = tid >> 2;
    const int ldR1 = (tid + NTHREADS) >> 2;
    const int ldKC = (tid & 3) * 16;
    const uint32_t sOff0 = (uint32_t)ldR0 * SSTRB + (uint32_t)ldKC;
    const uint32_t sOff1 = (uint32_t)ldR1 * SSTRB + (uint32_t)ldKC;

    auto load_chunk = [&](int rb, int cb, int c, int slot) {
        const uint32_t aBase = sbase + SM_A + (uint32_t)slot * STAGE_OP_BYTES;
        const uint32_t bBase = sbase + SM_B + (uint32_t)slot * STAGE_OP_BYTES;
        const uint32_t gk = (uint32_t)(c * BK + ldKC);
        const uint8_t* ga0 = Xb + (uint32_t)(rb * BM + ldR0) * (uint32_t)d + gk;
        const uint8_t* ga1 = Xb + (uint32_t)(rb * BM + ldR1) * (uint32_t)d + gk;
        const uint8_t* gb0 = Xb + (uint32_t)(cb * BN + ldR0) * (uint32_t)d + gk;
        const uint8_t* gb1 = Xb + (uint32_t)(cb * BN + ldR1) * (uint32_t)d + gk;
        CP_ASYNC16(aBase + sOff0, ga0);
        CP_ASYNC16(aBase + sOff1, ga1);
        CP_ASYNC16(bBase + sOff0, gb0);
        CP_ASYNC16(bBase + sOff1, gb1);
    };

    float acc[2][8][4];
#pragma unroll
    for (int mt = 0; mt < 2; mt++)
#pragma unroll
        for (int ntile = 0; ntile < 8; ntile++)
#pragma unroll
            for (int e = 0; e < 4; e++) acc[mt][ntile][e] = 0.0f;

    const uint32_t laneRow = (uint32_t)(lane & 15) * SSTRB;
    const uint32_t laneK = (uint32_t)(lane >> 4) * 16;
    const uint32_t aLane = (uint32_t)(warpM * 32) * SSTRB + laneRow + laneK;
    const uint32_t bLane = (uint32_t)(warpN * 64) * SSTRB + laneRow + laneK;

    float s1 = 0.0f, s2 = 0.0f;
    unsigned int cnt = 0;

    int cpK = 0, cpRB = 0, cpCB = 0;
    int ldK = 0, ldRB = 0, ldCB = 0;
    if (myTiles > 0) {
        decode_tile(blockIdx.x, nt, cpRB, cpCB);
        ldRB = cpRB;
        ldCB = cpCB;
    }

    // Prefetch 3 chunks (all within tile 0 since nChunks >= 4).
#pragma unroll
    for (int p = 0; p < 3; p++) {
        if (p < total) load_chunk(ldRB, ldCB, p, p & (NSTG - 1));
        CP_COMMIT();
    }

    for (int gs = 0; gs < total; gs++) {
        const int c = gs & (nChunks - 1);
        CP_WAIT2();      // commits = gs+3; 2 newest pending => chunk gs done
        __syncthreads();

        if (c == 0) {
            int i = tid & 127;
            if (tid < 128) {
                sqA[i] = g_sq[cpRB * BM + i];
                labA[i] = lab[cpRB * BM + i];
            } else {
                sqB[i] = g_sq[cpCB * BN + i];
                labB[i] = lab[cpCB * BN + i];
            }
        }

        const int gl = gs + 3;
        if (gl < total) {
            const int lk = gl / nChunks;
            if (lk != ldK) {
                ldK = lk;
                decode_tile(blockIdx.x + lk * stride, nt, ldRB, ldCB);
            }
            load_chunk(ldRB, ldCB, gl & (nChunks - 1), gl & (NSTG - 1));
        }
        CP_COMMIT();  // always commit to keep group counts aligned

        const uint32_t stBase = (uint32_t)(gs & (NSTG - 1)) * STAGE_OP_BYTES;
        const uint32_t aBase = sbase + SM_A + stBase + aLane;
        const uint32_t bBase = sbase + SM_B + stBase + bLane;

        uint32_t a[2][2][4];
#pragma unroll
        for (int mt = 0; mt < 2; mt++)
#pragma unroll
            for (int ks = 0; ks < 2; ks++)
                LDSM_X4(a[mt][ks][0], a[mt][ks][1], a[mt][ks][2], a[mt][ks][3],
                        aBase + (uint32_t)mt * 16 * SSTRB + (uint32_t)ks * 32);

#pragma unroll
        for (int ks = 0; ks < 2; ks++) {
#pragma unroll
            for (int ntp = 0; ntp < 4; ntp++) {
                uint32_t r0, r1, r2, r3;
                LDSM_X4(r0, r1, r2, r3,
                        bBase + (uint32_t)ntp * 16 * SSTRB + (uint32_t)ks * 32);
#pragma unroll
                for (int mt = 0; mt < 2; mt++) {
                    MMA16832(acc[mt][2 * ntp + 0], a[mt][ks][0], a[mt][ks][1],
                             a[mt][ks][2], a[mt][ks][3], r0, r2);
                    MMA16832(acc[mt][2 * ntp + 1], a[mt][ks][0], a[mt][ks][1],
                             a[mt][ks][2], a[mt][ks][3], r1, r3);
                }
            }
        }

        if (c == nChunks - 1) {
            const int rowBase = cpRB * BM, colBase = cpCB * BN;
            const bool diag = (cpRB == cpCB);
#pragma unroll
            for (int mt = 0; mt < 2; mt++) {
                const int i0 = warpM * 32 + mt * 16 + (lane >> 2);
#pragma unroll
                for (int half = 0; half < 2; half++) {
                    const int iloc = i0 + half * 8;
                    const int gi = rowBase + iloc;
                    const float sqi = sqA[iloc];
                    const int li = labA[iloc];
#pragma unroll
                    for (int ntile = 0; ntile < 8; ntile++) {
#pragma unroll
                        for (int e = 0; e < 2; e++) {
                            const int jloc =
                                warpN * 64 + ntile * 8 + (lane & 3) * 2 + e;
                            const int gj = colBase + jloc;
                            float w = 2.0f;
                            if (diag)
                                w = (gi > gj) ? 0.0f : ((gi == gj) ? 1.0f : 2.0f);
                            if (w != 0.0f) {
                                float D = sqi + sqB[jloc] -
                                          2.0f * acc[mt][ntile][half * 2 + e];
                                D = fmaxf(D, 0.0f);
                                if (li == labB[jloc]) {
                                    s1 += w * D;
                                    cnt += (unsigned int)w;
                                } else {
                                    s2 += w * fmaxf(0.0f, margin - D);
                                }
                            }
                            acc[mt][ntile][half * 2 + e] = 0.0f;
                        }
                    }
                }
            }
            cpK++;
            if (cpK < myTiles)
                decode_tile(blockIdx.x + cpK * stride, nt, cpRB, cpCB);
        }
    }

    // One block reduction + atomics per CTA.
#pragma unroll
    for (int o = 16; o > 0; o >>= 1) {
        s1 += __shfl_down_sync(0xffffffffu, s1, o);
        s2 += __shfl_down_sync(0xffffffffu, s2, o);
        cnt += __shfl_down_sync(0xffffffffu, cnt, o);
    }
    float* r1 = reinterpret_cast<float*>(smem + SM_RED);
    float* r2 = r1 + 8;
    unsigned int* rc = reinterpret_cast<unsigned int*>(r2 + 8);
    __syncthreads();
    if (lane == 0) {
        r1[wid] = s1;
        r2[wid] = s2;
        rc[wid] = cnt;
    }
    __syncthreads();
    if (tid == 0) {
        double t1 = 0.0, t2 = 0.0;
        unsigned int tc = 0;
#pragma unroll
        for (int w = 0; w < 8; w++) {
            t1 += (double)r1[w];
            t2 += (double)r2[w];
            tc += rc[w];
        }
        atomicAdd(&g_sum1, t1);
        atomicAdd(&g_sum2, t2);
        atomicAdd(&g_cnt, (unsigned long long)tc);

        __threadfence();
        unsigned int old = atomicAdd(&g_done, 1u);
        if (old == gridDim.x - 1) {
            double zn1 = (double)atomicAdd(&g_cnt, 0ull);
            double t1f = atomicAdd(&g_sum1, 0.0);
            double t2f = atomicAdd(&g_sum2, 0.0);
            double zn2 = (double)n * (double)n - zn1;
            out[0] = (float)(0.5 * (t1f / zn1 + t2f / zn2));
            g_done = 0u;
        }
    }
}

extern "C" void kernel_launch(void* const* d_in, const int* in_sizes, int n_in,
                              void* d_out, int out_size) {
    const float* X = (const float*)d_in[0];
    const int* lab = (const int*)d_in[1];
    const float* marginp = (const float*)d_in[2];
    float* out = (float*)d_out;

    int n = in_sizes[1];
    int d = in_sizes[0] / n;

    cudaFuncSetAttribute(pair_kernel,
                         cudaFuncAttributeMaxDynamicSharedMemorySize, SMEM_TOTAL);

    convert_kernel<<<(n + 3) / 4, 128>>>(X, n, d);

    int nt = (n + BM - 1) / BM;
    int nb = nt * (nt + 1) / 2;
    int ctas = nb < 296 ? nb : 296;  // up to 2 persistent CTAs per SM
    pair_kernel<<<ctas, NTHREADS, SMEM_TOTAL>>>(lab, marginp, out, n, d, nt, nb);
}

// round 11
// speedup vs baseline: 1.3167x; 1.3167x over previous
#include <cuda_runtime.h>
#include <cstdint>

// FeaturesLoss via mma.sync e4m3 m16n8k32 (compute_103-safe), persistent CTAs.
// R11: register diet — per-ks A fragment loads + 32-bit loader offsets — to fit
// true demand under the (256,2) cap: 2 CTAs/SM AND zero spill together.

#define BM 128
#define BN 128
#define BK 64            // fp8 bytes per K-chunk
#define NTHREADS 256
#define MAXN 4096
#define MAXD 512
#define SSTRB 80         // smem row stride bytes: conflict-free 16B granules
#define NSTG 3

#define STAGE_OP_BYTES (BM * SSTRB)          // 10240 per operand per stage
#define SM_A 0
#define SM_B (NSTG * STAGE_OP_BYTES)          // 30720
#define SM_SQA (2 * NSTG * STAGE_OP_BYTES)    // 61440
#define SM_SQB (SM_SQA + 512)
#define SM_LABA (SM_SQB + 512)
#define SM_LABB (SM_LABA + 512)
#define SM_RED (SM_LABB + 512)
#define SMEM_TOTAL (SM_RED + 128)             // 63616

__device__ float g_sq[MAXN];
__device__ __align__(16) uint8_t g_Xf8[MAXN * MAXD];
__device__ double g_sum1;
__device__ double g_sum2;
__device__ unsigned long long g_cnt;
__device__ unsigned int g_done;

__device__ __forceinline__ uint32_t smem_u32(const void* p) {
    uint32_t a;
    asm("{ .reg .u64 t; cvta.to.shared.u64 t, %1; cvt.u32.u64 %0, t; }"
        : "=r"(a) : "l"(p));
    return a;
}

#define CP_ASYNC16(dst_u32, src) \
    asm volatile("cp.async.cg.shared.global [%0], [%1], 16;" :: "r"(dst_u32), "l"(src))
#define CP_COMMIT() asm volatile("cp.async.commit_group;" ::: "memory")
#define CP_WAIT1()  asm volatile("cp.async.wait_group 1;" ::: "memory")

#define LDSM_X4(r0, r1, r2, r3, a)                                        \
    asm volatile("ldmatrix.sync.aligned.m8n8.x4.shared.b16 "              \
                 "{%0,%1,%2,%3}, [%4];"                                   \
                 : "=r"(r0), "=r"(r1), "=r"(r2), "=r"(r3) : "r"(a))

#define MMA16832(c, a0, a1, a2, a3, b0, b1)                               \
    asm volatile("mma.sync.aligned.m16n8k32.row.col.f32.e4m3.e4m3.f32 "   \
                 "{%0,%1,%2,%3}, {%4,%5,%6,%7}, {%8,%9}, {%0,%1,%2,%3};"  \
                 : "+f"((c)[0]), "+f"((c)[1]), "+f"((c)[2]), "+f"((c)[3]) \
                 : "r"(a0), "r"(a1), "r"(a2), "r"(a3), "r"(b0), "r"(b1))

__device__ __forceinline__ uint32_t pack_e4m3x4(float4 v) {
    uint16_t lo, hi;
    asm("cvt.rn.satfinite.e4m3x2.f32 %0, %1, %2;" : "=h"(lo) : "f"(v.y), "f"(v.x));
    asm("cvt.rn.satfinite.e4m3x2.f32 %0, %1, %2;" : "=h"(hi) : "f"(v.w), "f"(v.z));
    return (uint32_t)lo | ((uint32_t)hi << 16);
}

__device__ __forceinline__ void decode_tile(int t, int nt, int& br, int& bc) {
    int b = t, r = 0, rl = nt;
    while (b >= rl) {
        b -= rl;
        rl--;
        r++;
    }
    br = r;
    bc = r + b;
}

// ---------------------------------------------------------------------------
// Kernel A: X -> e4m3 + exact fp32 row norms. One warp per row.
// ---------------------------------------------------------------------------
__global__ void __launch_bounds__(128) convert_kernel(const float* __restrict__ X,
                                                      int n, int d) {
    if (blockIdx.x == 0 && threadIdx.x == 0) {
        g_sum1 = 0.0;
        g_sum2 = 0.0;
        g_cnt = 0ull;
        g_done = 0u;
    }
    const int w = threadIdx.x >> 5, l = threadIdx.x & 31;
    const int row = blockIdx.x * 4 + w;
    if (row >= n) return;
    const float4* src = reinterpret_cast<const float4*>(X + (size_t)row * d);
    uint32_t* dst = reinterpret_cast<uint32_t*>(g_Xf8 + (size_t)row * d);
    float s = 0.0f;
    if (d == 512) {
        float4 v[4];
#pragma unroll
        for (int i = 0; i < 4; i++) v[i] = src[l + 32 * i];
#pragma unroll
        for (int i = 0; i < 4; i++) {
            s = fmaf(v[i].x, v[i].x,
                     fmaf(v[i].y, v[i].y,
                          fmaf(v[i].z, v[i].z, fmaf(v[i].w, v[i].w, s))));
            dst[l + 32 * i] = pack_e4m3x4(v[i]);
        }
    } else {
        for (int c4 = l; c4 * 4 < d; c4 += 32) {
            float4 v = src[c4];
            s = fmaf(v.x, v.x, fmaf(v.y, v.y, fmaf(v.z, v.z, fmaf(v.w, v.w, s))));
            dst[c4] = pack_e4m3x4(v);
        }
    }
#pragma unroll
    for (int o = 16; o > 0; o >>= 1) s += __shfl_down_sync(0xffffffffu, s, o);
    if (l == 0) g_sq[row] = s;
}

// ---------------------------------------------------------------------------
// Kernel B: persistent fp8 Gram over tile stream + fused epilogue + finalize.
// ---------------------------------------------------------------------------
__global__ void __launch_bounds__(NTHREADS, 2) pair_kernel(
    const int* __restrict__ lab, const float* __restrict__ marginp,
    float* __restrict__ out, int n, int d, int nt, int nb) {
    extern __shared__ __align__(1024) uint8_t smem[];
    const uint32_t sbase = smem_u32(smem);
    float* sqA = reinterpret_cast<float*>(smem + SM_SQA);
    float* sqB = reinterpret_cast<float*>(smem + SM_SQB);
    int* labA = reinterpret_cast<int*>(smem + SM_LABA);
    int* labB = reinterpret_cast<int*>(smem + SM_LABB);

    const int tid = threadIdx.x;
    const int wid = tid >> 5, lane = tid & 31;
    const int warpM = wid & 3;   // 4 warps over M: 32 rows each
    const int warpN = wid >> 2;  // 2 warps over N: 64 cols each

    const int nChunks = d / BK;  // 8 for d=512
    const int stride = gridDim.x;
    int myTiles = 0;
    for (int t = blockIdx.x; t < nb; t += stride) myTiles++;
    const int total = myTiles * nChunks;

    const uint8_t* __restrict__ Xb = g_Xf8;
    const float margin = *marginp;

    // Per-thread load-slot geometry (constant).
    const int ldR0 = tid >> 2;
    const int ldR1 = (tid + NTHREADS) >> 2;
    const int ldKC = (tid & 3) * 16;
    const uint32_t sOff0 = (uint32_t)ldR0 * SSTRB + (uint32_t)ldKC;
    const uint32_t sOff1 = (uint32_t)ldR1 * SSTRB + (uint32_t)ldKC;

    // Cached 32-bit global row offsets for the CURRENT load tile; refreshed on
    // tile advance. off = row * d + ldKC.
    uint32_t gA0 = 0, gA1 = 0, gB0 = 0, gB1 = 0;

    auto set_load_tile = [&](int rb, int cb) {
        gA0 = (uint32_t)(rb * BM + ldR0) * (uint32_t)d + (uint32_t)ldKC;
        gA1 = (uint32_t)(rb * BM + ldR1) * (uint32_t)d + (uint32_t)ldKC;
        gB0 = (uint32_t)(cb * BN + ldR0) * (uint32_t)d + (uint32_t)ldKC;
        gB1 = (uint32_t)(cb * BN + ldR1) * (uint32_t)d + (uint32_t)ldKC;
    };

    auto load_chunk = [&](int c, int slot) {
        const uint32_t aBase = sbase + SM_A + (uint32_t)slot * STAGE_OP_BYTES;
        const uint32_t bBase = sbase + SM_B + (uint32_t)slot * STAGE_OP_BYTES;
        const uint32_t ck = (uint32_t)(c * BK);
        CP_ASYNC16(aBase + sOff0, Xb + gA0 + ck);
        CP_ASYNC16(aBase + sOff1, Xb + gA1 + ck);
        CP_ASYNC16(bBase + sOff0, Xb + gB0 + ck);
        CP_ASYNC16(bBase + sOff1, Xb + gB1 + ck);
    };

    float acc[2][8][4];
#pragma unroll
    for (int mt = 0; mt < 2; mt++)
#pragma unroll
        for (int ntile = 0; ntile < 8; ntile++)
#pragma unroll
            for (int e = 0; e < 4; e++) acc[mt][ntile][e] = 0.0f;

    const uint32_t laneRow = (uint32_t)(lane & 15) * SSTRB;
    const uint32_t laneK = (uint32_t)(lane >> 4) * 16;
    const uint32_t aLane = (uint32_t)(warpM * 32) * SSTRB + laneRow + laneK;
    const uint32_t bLane = (uint32_t)(warpN * 64) * SSTRB + laneRow + laneK;

    float s1 = 0.0f, s2 = 0.0f;
    unsigned int cnt = 0;

    int cpK = 0, cpRB = 0, cpCB = 0;
    int ldK = 0;
    if (myTiles > 0) {
        decode_tile(blockIdx.x, nt, cpRB, cpCB);
        set_load_tile(cpRB, cpCB);
    }

#pragma unroll
    for (int p = 0; p < 2; p++) {
        if (p < total) load_chunk(p, p % NSTG);
        CP_COMMIT();
    }

    for (int gs = 0; gs < total; gs++) {
        const int c = gs & (nChunks - 1);
        CP_WAIT1();
        __syncthreads();

        if (c == 0) {
            int i = tid & 127;
            if (tid < 128) {
                sqA[i] = g_sq[cpRB * BM + i];
                labA[i] = lab[cpRB * BM + i];
            } else {
                sqB[i] = g_sq[cpCB * BN + i];
                labB[i] = lab[cpCB * BN + i];
            }
        }

        const int gl = gs + 2;
        if (gl < total) {
            const int lk = gl / nChunks;
            if (lk != ldK) {
                ldK = lk;
                int rb, cb;
                decode_tile(blockIdx.x + lk * stride, nt, rb, cb);
                set_load_tile(rb, cb);
            }
            load_chunk(gl & (nChunks - 1), gl % NSTG);
        }
        CP_COMMIT();

        const uint32_t stBase = (uint32_t)(gs % NSTG) * STAGE_OP_BYTES;
        const uint32_t aBase = sbase + SM_A + stBase + aLane;
        const uint32_t bBase = sbase + SM_B + stBase + bLane;

        // Per-ks A loads (half the A-frag registers live at once).
#pragma unroll
        for (int ks = 0; ks < 2; ks++) {
            uint32_t a[2][4];
#pragma unroll
            for (int mt = 0; mt < 2; mt++)
                LDSM_X4(a[mt][0], a[mt][1], a[mt][2], a[mt][3],
                        aBase + (uint32_t)mt * 16 * SSTRB + (uint32_t)ks * 32);
#pragma unroll
            for (int ntp = 0; ntp < 4; ntp++) {
                uint32_t r0, r1, r2, r3;
                LDSM_X4(r0, r1, r2, r3,
                        bBase + (uint32_t)ntp * 16 * SSTRB + (uint32_t)ks * 32);
#pragma unroll
                for (int mt = 0; mt < 2; mt++) {
                    MMA16832(acc[mt][2 * ntp + 0], a[mt][0], a[mt][1], a[mt][2],
                             a[mt][3], r0, r2);
                    MMA16832(acc[mt][2 * ntp + 1], a[mt][0], a[mt][1], a[mt][2],
                             a[mt][3], r1, r3);
                }
            }
        }

        if (c == nChunks - 1) {
            const int rowBase = cpRB * BM, colBase = cpCB * BN;
            const bool diag = (cpRB == cpCB);
#pragma unroll
            for (int mt = 0; mt < 2; mt++) {
                const int i0 = warpM * 32 + mt * 16 + (lane >> 2);
#pragma unroll
                for (int half = 0; half < 2; half++) {
                    const int iloc = i0 + half * 8;
                    const int gi = rowBase + iloc;
                    const float sqi = sqA[iloc];
                    const int li = labA[iloc];
#pragma unroll
                    for (int ntile = 0; ntile < 8; ntile++) {
#pragma unroll
                        for (int e = 0; e < 2; e++) {
                            const int jloc =
                                warpN * 64 + ntile * 8 + (lane & 3) * 2 + e;
                            const int gj = colBase + jloc;
                            float w = 2.0f;
                            if (diag)
                                w = (gi > gj) ? 0.0f : ((gi == gj) ? 1.0f : 2.0f);
                            if (w != 0.0f) {
                                float D = sqi + sqB[jloc] -
                                          2.0f * acc[mt][ntile][half * 2 + e];
                                D = fmaxf(D, 0.0f);
                                if (li == labB[jloc]) {
                                    s1 += w * D;
                                    cnt += (unsigned int)w;
                                } else {
                                    s2 += w * fmaxf(0.0f, margin - D);
                                }
                            }
                            acc[mt][ntile][half * 2 + e] = 0.0f;
                        }
                    }
                }
            }
            cpK++;
            if (cpK < myTiles) {
                decode_tile(blockIdx.x + cpK * stride, nt, cpRB, cpCB);
            }
        }
    }

    // One block reduction + atomics per CTA.
#pragma unroll
    for (int o = 16; o > 0; o >>= 1) {
        s1 += __shfl_down_sync(0xffffffffu, s1, o);
        s2 += __shfl_down_sync(0xffffffffu, s2, o);
        cnt += __shfl_down_sync(0xffffffffu, cnt, o);
    }
    float* r1 = reinterpret_cast<float*>(smem + SM_RED);
    float* r2 = r1 + 8;
    unsigned int* rc = reinterpret_cast<unsigned int*>(r2 + 8);
    __syncthreads();
    if (lane == 0) {
        r1[wid] = s1;
        r2[wid] = s2;
        rc[wid] = cnt;
    }
    __syncthreads();
    if (tid == 0) {
        double t1 = 0.0, t2 = 0.0;
        unsigned int tc = 0;
#pragma unroll
        for (int w = 0; w < 8; w++) {
            t1 += (double)r1[w];
            t2 += (double)r2[w];
            tc += rc[w];
        }
        atomicAdd(&g_sum1, t1);
        atomicAdd(&g_sum2, t2);
        atomicAdd(&g_cnt, (unsigned long long)tc);

        __threadfence();
        unsigned int old = atomicAdd(&g_done, 1u);
        if (old == gridDim.x - 1) {
            double zn1 = (double)atomicAdd(&g_cnt, 0ull);
            double t1f = atomicAdd(&g_sum1, 0.0);
            double t2f = atomicAdd(&g_sum2, 0.0);
            double zn2 = (double)n * (double)n - zn1;
            out[0] = (float)(0.5 * (t1f / zn1 + t2f / zn2));
            g_done = 0u;
        }
    }
}

extern "C" void kernel_launch(void* const* d_in, const int* in_sizes, int n_in,
                              void* d_out, int out_size) {
    const float* X = (const float*)d_in[0];
    const int* lab = (const int*)d_in[1];
    const float* marginp = (const float*)d_in[2];
    float* out = (float*)d_out;

    int n = in_sizes[1];
    int d = in_sizes[0] / n;

    cudaFuncSetAttribute(pair_kernel,
                         cudaFuncAttributeMaxDynamicSharedMemorySize, SMEM_TOTAL);

    convert_kernel<<<(n + 3) / 4, 128>>>(X, n, d);

    int nt = (n + BM - 1) / BM;
    int nb = nt * (nt + 1) / 2;
    int ctas = nb < 296 ? nb : 296;  // 2 persistent CTAs per SM
    pair_kernel<<<ctas, NTHREADS, SMEM_TOTAL>>>(lab, marginp, out, n, d, nt, nb);
}

// round 12
// speedup vs baseline: 1.3390x; 1.0169x over previous
#include <cuda_runtime.h>
#include <cstdint>

// FeaturesLoss via mma.sync e4m3 m16n8k32, persistent CTAs.
// R12: 3 CTAs/SM (warp tile 32x32, acc=32 regs) + BK=128 (half the barriers).

#define BM 128
#define BN 64
#define BK 128           // fp8 bytes per K-chunk = full row
#define NTHREADS 256
#define MAXN 4096
#define MAXD 512
#define SSTRB 144        // 128+16 bytes: odd 16B-granule stride, conflict-free
#define NSTG 2

#define STAGE_A_BYTES (BM * SSTRB)           // 18432
#define STAGE_B_BYTES (BN * SSTRB)           // 9216
#define SM_A 0
#define SM_B (NSTG * STAGE_A_BYTES)           // 36864
#define SM_SQA (SM_B + NSTG * STAGE_B_BYTES)  // 55296
#define SM_SQB (SM_SQA + 512)
#define SM_LABA (SM_SQB + 256)
#define SM_LABB (SM_LABA + 512)
#define SM_RED (SM_LABB + 256)
#define SMEM_TOTAL (SM_RED + 128)             // 56960

__device__ float g_sq[MAXN];
__device__ __align__(16) uint8_t g_Xf8[MAXN * MAXD];
__device__ double g_sum1;
__device__ double g_sum2;
__device__ unsigned long long g_cnt;
__device__ unsigned int g_done;

__device__ __forceinline__ uint32_t smem_u32(const void* p) {
    uint32_t a;
    asm("{ .reg .u64 t; cvta.to.shared.u64 t, %1; cvt.u32.u64 %0, t; }"
        : "=r"(a) : "l"(p));
    return a;
}

#define CP_ASYNC16(dst_u32, src) \
    asm volatile("cp.async.cg.shared.global [%0], [%1], 16;" :: "r"(dst_u32), "l"(src))
#define CP_COMMIT() asm volatile("cp.async.commit_group;" ::: "memory")
#define CP_WAIT0()  asm volatile("cp.async.wait_group 0;" ::: "memory")

#define LDSM_X4(r0, r1, r2, r3, a)                                        \
    asm volatile("ldmatrix.sync.aligned.m8n8.x4.shared.b16 "              \
                 "{%0,%1,%2,%3}, [%4];"                                   \
                 : "=r"(r0), "=r"(r1), "=r"(r2), "=r"(r3) : "r"(a))

#define MMA16832(c, a0, a1, a2, a3, b0, b1)                               \
    asm volatile("mma.sync.aligned.m16n8k32.row.col.f32.e4m3.e4m3.f32 "   \
                 "{%0,%1,%2,%3}, {%4,%5,%6,%7}, {%8,%9}, {%0,%1,%2,%3};"  \
                 : "+f"((c)[0]), "+f"((c)[1]), "+f"((c)[2]), "+f"((c)[3]) \
                 : "r"(a0), "r"(a1), "r"(a2), "r"(a3), "r"(b0), "r"(b1))

__device__ __forceinline__ uint32_t pack_e4m3x4(float4 v) {
    uint16_t lo, hi;
    asm("cvt.rn.satfinite.e4m3x2.f32 %0, %1, %2;" : "=h"(lo) : "f"(v.y), "f"(v.x));
    asm("cvt.rn.satfinite.e4m3x2.f32 %0, %1, %2;" : "=h"(hi) : "f"(v.w), "f"(v.z));
    return (uint32_t)lo | ((uint32_t)hi << 16);
}

// Blocks (br, bc) with bc in [2*br, ntn): rl starts at ntn, shrinks by 2.
__device__ __forceinline__ void decode_tile(int t, int ntn, int& br, int& bc) {
    int b = t, r = 0, rl = ntn;
    while (b >= rl) {
        b -= rl;
        rl -= 2;
        r++;
    }
    br = r;
    bc = 2 * r + b;
}

// ---------------------------------------------------------------------------
// Kernel A: X -> e4m3 + exact fp32 row norms. One warp per row.
// ---------------------------------------------------------------------------
__global__ void __launch_bounds__(128) convert_kernel(const float* __restrict__ X,
                                                      int n, int d) {
    if (blockIdx.x == 0 && threadIdx.x == 0) {
        g_sum1 = 0.0;
        g_sum2 = 0.0;
        g_cnt = 0ull;
        g_done = 0u;
    }
    const int w = threadIdx.x >> 5, l = threadIdx.x & 31;
    const int row = blockIdx.x * 4 + w;
    if (row >= n) return;
    const float4* src = reinterpret_cast<const float4*>(X + (size_t)row * d);
    uint32_t* dst = reinterpret_cast<uint32_t*>(g_Xf8 + (size_t)row * d);
    float s = 0.0f;
    if (d == 512) {
        float4 v[4];
#pragma unroll
        for (int i = 0; i < 4; i++) v[i] = src[l + 32 * i];
#pragma unroll
        for (int i = 0; i < 4; i++) {
            s = fmaf(v[i].x, v[i].x,
                     fmaf(v[i].y, v[i].y,
                          fmaf(v[i].z, v[i].z, fmaf(v[i].w, v[i].w, s))));
            dst[l + 32 * i] = pack_e4m3x4(v[i]);
        }
    } else {
        for (int c4 = l; c4 * 4 < d; c4 += 32) {
            float4 v = src[c4];
            s = fmaf(v.x, v.x, fmaf(v.y, v.y, fmaf(v.z, v.z, fmaf(v.w, v.w, s))));
            dst[c4] = pack_e4m3x4(v);
        }
    }
#pragma unroll
    for (int o = 16; o > 0; o >>= 1) s += __shfl_down_sync(0xffffffffu, s, o);
    if (l == 0) g_sq[row] = s;
}

// ---------------------------------------------------------------------------
// Kernel B: persistent fp8 Gram (128x64 blocks) + fused epilogue + finalize.
// ---------------------------------------------------------------------------
__global__ void __launch_bounds__(NTHREADS, 3) pair_kernel(
    const int* __restrict__ lab, const float* __restrict__ marginp,
    float* __restrict__ out, int n, int d, int ntn, int nb) {
    extern __shared__ __align__(1024) uint8_t smem[];
    const uint32_t sbase = smem_u32(smem);
    float* sqA = reinterpret_cast<float*>(smem + SM_SQA);
    float* sqB = reinterpret_cast<float*>(smem + SM_SQB);
    int* labA = reinterpret_cast<int*>(smem + SM_LABA);
    int* labB = reinterpret_cast<int*>(smem + SM_LABB);

    const int tid = threadIdx.x;
    const int wid = tid >> 5, lane = tid & 31;
    const int warpM = wid & 3;   // 4 warps over M: 32 rows each
    const int warpN = wid >> 2;  // 2 warps over N: 32 cols each

    const int nChunks = d / BK;  // 4 for d=512
    const int stride = gridDim.x;
    int myTiles = 0;
    for (int t = blockIdx.x; t < nb; t += stride) myTiles++;
    const int total = myTiles * nChunks;

    const uint8_t* __restrict__ Xb = g_Xf8;
    const float margin = *marginp;

    // Loader geometry: piece index p = tid + 256*l; row = p>>3, kc = p&7.
    // Row slots differ by 32 per l -> +32*d in gmem, +32*SSTRB in smem.
    const int ldRow = tid >> 3;          // base row (l=0)
    const int ldKC = (tid & 7) * 16;     // 16B piece offset within the row
    const uint32_t sOffBase = (uint32_t)ldRow * SSTRB + (uint32_t)ldKC;
    uint32_t gAbase = 0, gBbase = 0;     // row*d + kc for current load tile

    auto set_load_tile = [&](int rb, int cb) {
        gAbase = (uint32_t)(rb * BM + ldRow) * (uint32_t)d + (uint32_t)ldKC;
        gBbase = (uint32_t)(cb * BN + ldRow) * (uint32_t)d + (uint32_t)ldKC;
    };

    auto load_chunk = [&](int c, int slot) {
        const uint32_t aB = sbase + SM_A + (uint32_t)slot * STAGE_A_BYTES;
        const uint32_t bB = sbase + SM_B + (uint32_t)slot * STAGE_B_BYTES;
        const uint32_t ck = (uint32_t)(c * BK);
#pragma unroll
        for (int l = 0; l < 4; l++)  // A: 128 rows
            CP_ASYNC16(aB + sOffBase + (uint32_t)l * (32 * SSTRB),
                       Xb + gAbase + ck + (uint32_t)l * 32 * (uint32_t)d);
#pragma unroll
        for (int l = 0; l < 2; l++)  // B: 64 rows
            CP_ASYNC16(bB + sOffBase + (uint32_t)l * (32 * SSTRB),
                       Xb + gBbase + ck + (uint32_t)l * 32 * (uint32_t)d);
    };

    float acc[2][4][4];  // [mt][ntile][e]
#pragma unroll
    for (int mt = 0; mt < 2; mt++)
#pragma unroll
        for (int ntile = 0; ntile < 4; ntile++)
#pragma unroll
            for (int e = 0; e < 4; e++) acc[mt][ntile][e] = 0.0f;

    const uint32_t laneRow = (uint32_t)(lane & 15) * SSTRB;
    const uint32_t laneK = (uint32_t)(lane >> 4) * 16;
    const uint32_t aLane = (uint32_t)(warpM * 32) * SSTRB + laneRow + laneK;
    const uint32_t bLane = (uint32_t)(warpN * 32) * SSTRB + laneRow + laneK;

    float s1 = 0.0f, s2 = 0.0f;
    unsigned int cnt = 0;

    int cpK = 0, cpRB = 0, cpCB = 0;
    int ldK = 0;
    if (myTiles > 0) {
        decode_tile(blockIdx.x, ntn, cpRB, cpCB);
        set_load_tile(cpRB, cpCB);
    }

    if (total > 0) load_chunk(0, 0);
    CP_COMMIT();

    for (int gs = 0; gs < total; gs++) {
        const int c = gs & (nChunks - 1);
        CP_WAIT0();
        __syncthreads();

        if (c == 0) {
            if (tid < 128) {
                sqA[tid] = g_sq[cpRB * BM + tid];
                labA[tid] = lab[cpRB * BM + tid];
            } else if (tid < 192) {
                int i = tid - 128;
                sqB[i] = g_sq[cpCB * BN + i];
                labB[i] = lab[cpCB * BN + i];
            }
        }

        const int gl = gs + 1;
        if (gl < total) {
            const int lk = gl / nChunks;
            if (lk != ldK) {
                ldK = lk;
                int rb, cb;
                decode_tile(blockIdx.x + lk * stride, ntn, rb, cb);
                set_load_tile(rb, cb);
            }
            load_chunk(gl & (nChunks - 1), gl & (NSTG - 1));
        }
        CP_COMMIT();

        const uint32_t slot = (uint32_t)(gs & (NSTG - 1));
        const uint32_t aBase = sbase + SM_A + slot * STAGE_A_BYTES + aLane;
        const uint32_t bBase = sbase + SM_B + slot * STAGE_B_BYTES + bLane;

        // BK=128 -> 4 k32-steps per chunk.
#pragma unroll
        for (int ks = 0; ks < 4; ks++) {
            uint32_t a[2][4];
#pragma unroll
            for (int mt = 0; mt < 2; mt++)
                LDSM_X4(a[mt][0], a[mt][1], a[mt][2], a[mt][3],
                        aBase + (uint32_t)mt * 16 * SSTRB + (uint32_t)ks * 32);
#pragma unroll
            for (int ntp = 0; ntp < 2; ntp++) {
                uint32_t r0, r1, r2, r3;
                LDSM_X4(r0, r1, r2, r3,
                        bBase + (uint32_t)ntp * 16 * SSTRB + (uint32_t)ks * 32);
#pragma unroll
                for (int mt = 0; mt < 2; mt++) {
                    MMA16832(acc[mt][2 * ntp + 0], a[mt][0], a[mt][1], a[mt][2],
                             a[mt][3], r0, r2);
                    MMA16832(acc[mt][2 * ntp + 1], a[mt][0], a[mt][1], a[mt][2],
                             a[mt][3], r1, r3);
                }
            }
        }

        if (c == nChunks - 1) {
            const int rowBase = cpRB * BM, colBase = cpCB * BN;
            const bool straddle = (cpCB - 2 * cpRB) < 2;  // block crosses diagonal
#pragma unroll
            for (int mt = 0; mt < 2; mt++) {
                const int i0 = warpM * 32 + mt * 16 + (lane >> 2);
#pragma unroll
                for (int half = 0; half < 2; half++) {
                    const int iloc = i0 + half * 8;
                    const int gi = rowBase + iloc;
                    const float sqi = sqA[iloc];
                    const int li = labA[iloc];
#pragma unroll
                    for (int ntile = 0; ntile < 4; ntile++) {
#pragma unroll
                        for (int e = 0; e < 2; e++) {
                            const int jloc =
                                warpN * 32 + ntile * 8 + (lane & 3) * 2 + e;
                            const int gj = colBase + jloc;
                            float w = 2.0f;
                            if (straddle)
                                w = (gi > gj) ? 0.0f : ((gi == gj) ? 1.0f : 2.0f);
                            if (w != 0.0f) {
                                float D = sqi + sqB[jloc] -
                                          2.0f * acc[mt][ntile][half * 2 + e];
                                D = fmaxf(D, 0.0f);
                                if (li == labB[jloc]) {
                                    s1 += w * D;
                                    cnt += (unsigned int)w;
                                } else {
                                    s2 += w * fmaxf(0.0f, margin - D);
                                }
                            }
                            acc[mt][ntile][half * 2 + e] = 0.0f;
                        }
                    }
                }
            }
            cpK++;
            if (cpK < myTiles)
                decode_tile(blockIdx.x + cpK * stride, ntn, cpRB, cpCB);
        }
    }

    // One block reduction + atomics per CTA.
#pragma unroll
    for (int o = 16; o > 0; o >>= 1) {
        s1 += __shfl_down_sync(0xffffffffu, s1, o);
        s2 += __shfl_down_sync(0xffffffffu, s2, o);
        cnt += __shfl_down_sync(0xffffffffu, cnt, o);
    }
    float* r1 = reinterpret_cast<float*>(smem + SM_RED);
    float* r2 = r1 + 8;
    unsigned int* rc = reinterpret_cast<unsigned int*>(r2 + 8);
    __syncthreads();
    if (lane == 0) {
        r1[wid] = s1;
        r2[wid] = s2;
        rc[wid] = cnt;
    }
    __syncthreads();
    if (tid == 0) {
        double t1 = 0.0, t2 = 0.0;
        unsigned int tc = 0;
#pragma unroll
        for (int w = 0; w < 8; w++) {
            t1 += (double)r1[w];
            t2 += (double)r2[w];
            tc += rc[w];
        }
        atomicAdd(&g_sum1, t1);
        atomicAdd(&g_sum2, t2);
        atomicAdd(&g_cnt, (unsigned long long)tc);

        __threadfence();
        unsigned int old = atomicAdd(&g_done, 1u);
        if (old == gridDim.x - 1) {
            double zn1 = (double)atomicAdd(&g_cnt, 0ull);
            double t1f = atomicAdd(&g_sum1, 0.0);
            double t2f = atomicAdd(&g_sum2, 0.0);
            double zn2 = (double)n * (double)n - zn1;
            out[0] = (float)(0.5 * (t1f / zn1 + t2f / zn2));
            g_done = 0u;
        }
    }
}

extern "C" void kernel_launch(void* const* d_in, const int* in_sizes, int n_in,
                              void* d_out, int out_size) {
    const float* X = (const float*)d_in[0];
    const int* lab = (const int*)d_in[1];
    const float* marginp = (const float*)d_in[2];
    float* out = (float*)d_out;

    int n = in_sizes[1];
    int d = in_sizes[0] / n;

    cudaFuncSetAttribute(pair_kernel,
                         cudaFuncAttributeMaxDynamicSharedMemorySize, SMEM_TOTAL);

    convert_kernel<<<(n + 3) / 4, 128>>>(X, n, d);

    int ntm = n / BM;                       // 32
    int ntn = n / BN;                       // 64
    int nb = ntm * ntn - ntm * (ntm - 1);   // 1056 blocks of 128x64
    int ctas = nb < 444 ? nb : 444;         // 3 persistent CTAs per SM
    pair_kernel<<<ctas, NTHREADS, SMEM_TOTAL>>>(lab, marginp, out, n, d, ntn, nb);
}